// round 4
// baseline (speedup 1.0000x reference)
#include <cuda_runtime.h>
#include <cuda_fp16.h>
#include <cstdint>

// ---------------- problem constants ----------------
#define MDIM 8192      // B*S = 4*2048
#define NDIM 16384     // D_OUT
#define KDIM 4096      // D_IN

#define BM 128
#define BN 128
#define BK 64
#define STAGES 4
#define NKCHUNK (KDIM / BK)   // 64
#define THREADS 256

// SMEM layout (dynamic): A stages then B stages, 128B rows, SW128 swizzle
#define A_BYTES (BM * 128)                 // 16384
#define B_BYTES (BN * 128)                 // 16384
#define SMEM_A  0
#define SMEM_B  (STAGES * A_BYTES)         // 65536
#define SMEM_TOTAL (SMEM_B + STAGES * B_BYTES)  // 131072

// static device scratch (allocation-free rule): dequantized W (fp16) + x (fp16)
__device__ __half g_wdeq[(size_t)NDIM * KDIM];   // 128 MiB
__device__ __half g_xh[(size_t)MDIM * KDIM];     // 64 MiB

// ---------------- PTX helpers (compute_103-safe only) ----------------
__device__ __forceinline__ uint32_t smem_u32(const void* p) {
    uint32_t a;
    asm("{ .reg .u64 t; cvta.to.shared.u64 t, %1; cvt.u32.u64 %0, t; }" : "=r"(a) : "l"(p));
    return a;
}

__device__ __forceinline__ uint32_t swz128(uint32_t b) {
    return b ^ ((b >> 3) & 0x70);
}

__device__ __forceinline__ void cp_async16(uint32_t dst, const void* src) {
    asm volatile("cp.async.cg.shared.global [%0], [%1], 16;" :: "r"(dst), "l"(src));
}

__device__ __forceinline__ void ldsm4(uint32_t* r, uint32_t addr) {
    asm volatile("ldmatrix.sync.aligned.m8n8.x4.shared.b16 {%0,%1,%2,%3}, [%4];"
                 : "=r"(r[0]), "=r"(r[1]), "=r"(r[2]), "=r"(r[3]) : "r"(addr));
}

__device__ __forceinline__ void mma16816(float* c, const uint32_t* a, uint32_t b0, uint32_t b1) {
    asm volatile(
        "mma.sync.aligned.m16n8k16.row.col.f32.f16.f16.f32 "
        "{%0,%1,%2,%3}, {%4,%5,%6,%7}, {%8,%9}, {%0,%1,%2,%3};"
        : "+f"(c[0]), "+f"(c[1]), "+f"(c[2]), "+f"(c[3])
        : "r"(a[0]), "r"(a[1]), "r"(a[2]), "r"(a[3]), "r"(b0), "r"(b1));
}

// round fp32 accumulator through fp16 (match reference .astype(float16))
__device__ __forceinline__ float r16(float f) {
    return __half2float(__float2half_rn(f));
}

// ---------------- dequant kernel (int32 carrier -> fp16, exact fp16 math) ----
// one block per output row: 4096 int32 = 16 int4 loads x 256 threads
__global__ __launch_bounds__(256) void dequant_kernel(const int* __restrict__ w,
                                                      const float* __restrict__ sc,
                                                      const float* __restrict__ off) {
    int row = blockIdx.x;
    int t = threadIdx.x;
    __half2 s2 = __half2half2(__float2half(sc[row]));
    __half2 o2 = __half2half2(__float2half(off[row]));
    const int4* src = reinterpret_cast<const int4*>(w + (size_t)row * KDIM);
    __half2* dstrow = reinterpret_cast<__half2*>(g_wdeq + (size_t)row * KDIM);
#pragma unroll
    for (int u = 0; u < 4; u++) {
        int4 v = src[u * 256 + t];
        __half2 p0 = __halves2half2(__int2half_rn(v.x), __int2half_rn(v.y));
        __half2 p1 = __halves2half2(__int2half_rn(v.z), __int2half_rn(v.w));
        __half2 r0 = __hmul2(__hadd2(p0, o2), s2);
        __half2 r1 = __hmul2(__hadd2(p1, o2), s2);
        uint2 pk = make_uint2(*reinterpret_cast<uint32_t*>(&r0),
                              *reinterpret_cast<uint32_t*>(&r1));
        *reinterpret_cast<uint2*>(dstrow + (u * 256 + t) * 2) = pk;
    }
}

// ---------------- x convert kernel (fp32 -> fp16, exact) ----------------
__global__ __launch_bounds__(256) void xconv_kernel(const float* __restrict__ x) {
    size_t i = (size_t)blockIdx.x * 256 + threadIdx.x;   // one float4 each
    float4 v = reinterpret_cast<const float4*>(x)[i];
    __half2 h0 = __floats2half2_rn(v.x, v.y);
    __half2 h1 = __floats2half2_rn(v.z, v.w);
    uint2 pk = make_uint2(*reinterpret_cast<uint32_t*>(&h0),
                          *reinterpret_cast<uint32_t*>(&h1));
    reinterpret_cast<uint2*>(g_xh)[i] = pk;
}

// ---------------- stage loader ----------------
// A: BM(128) rows x 64 halfs (128B, SW128). B: BN(128) rows x 64 halfs.
__device__ __forceinline__ void load_stage(uint32_t sb, const __half* __restrict__ xh,
                                           const __half* __restrict__ wd,
                                           int m0, int n0, int chunk, int st, int tid) {
    int kc = chunk * BK;
    uint32_t a_base = sb + SMEM_A + st * A_BYTES;
#pragma unroll
    for (int i = 0; i < 4; i++) {
        int idx = i * THREADS + tid;      // 1024 x 16B
        int r = idx >> 3, seg = idx & 7;
        uint32_t dst = a_base + swz128(r * 128 + seg * 16);
        cp_async16(dst, xh + (size_t)(m0 + r) * KDIM + kc + seg * 8);
    }
    uint32_t b_base = sb + SMEM_B + st * B_BYTES;
#pragma unroll
    for (int i = 0; i < 4; i++) {
        int idx = i * THREADS + tid;      // 1024 x 16B
        int r = idx >> 3, seg = idx & 7;
        uint32_t dst = b_base + swz128(r * 128 + seg * 16);
        cp_async16(dst, wd + (size_t)(n0 + r) * KDIM + kc + seg * 8);
    }
}

// ---------------- HMMA GEMM kernel ----------------
__global__ __launch_bounds__(THREADS, 1) void gemm_kernel(float* __restrict__ out) {
    extern __shared__ char smem[];
    uint32_t sb = smem_u32(smem);
    int tid = threadIdx.x;
    int wid = tid >> 5, lane = tid & 31;
    int warp_m = wid & 3;       // 0..3
    int warp_n = wid >> 2;      // 0..1

    // tile mapping with GROUP_M=8 swizzle for L2 locality
    int pid = blockIdx.x;
    const int TM = MDIM / BM, TN = NDIM / BN;   // 64 x 128
    const int GROUP = 8;
    int per = GROUP * TN;
    int g = pid / per;
    int first = g * GROUP;
    int gsz = (GROUP < TM - first) ? GROUP : (TM - first);
    int mt = first + (pid % gsz);
    int nt = (pid % per) / gsz;
    int m0 = mt * BM, n0 = nt * BN;

    const __half* wd = g_wdeq;
    const __half* xh = g_xh;

    float acc[2][8][4];
#pragma unroll
    for (int i = 0; i < 2; i++)
#pragma unroll
        for (int j = 0; j < 8; j++)
#pragma unroll
            for (int q = 0; q < 4; q++) acc[i][j][q] = 0.0f;

    // ldmatrix x4 lane->address mapping:
    //   lanes 0-7: rows 0-7 k0-7 | 8-15: rows 8-15 k0-7 | 16-23: rows 0-7 k8-15 | 24-31: rows 8-15 k8-15
    int lrow = lane & 15;
    int khalf = lane >> 4;
    uint32_t aoff[2], boff[4];
#pragma unroll
    for (int i = 0; i < 2; i++)
        aoff[i] = (uint32_t)((warp_m * 32 + i * 16 + lrow) * 128 + khalf * 16);
#pragma unroll
    for (int j = 0; j < 4; j++)
        boff[j] = (uint32_t)((warp_n * 64 + j * 16 + lrow) * 128 + khalf * 16);

    // prologue: chunks 0..STAGES-2
#pragma unroll
    for (int s = 0; s < STAGES - 1; s++) {
        load_stage(sb, xh, wd, m0, n0, s, s, tid);
        asm volatile("cp.async.commit_group;");
    }

    for (int kt = 0; kt < NKCHUNK; kt++) {
        asm volatile("cp.async.wait_group 2;");   // chunk kt resident
        __syncthreads();

        // prefetch chunk kt+STAGES-1 into the stage freed at iter kt-1
        if (kt + STAGES - 1 < NKCHUNK)
            load_stage(sb, xh, wd, m0, n0, kt + STAGES - 1, (kt + STAGES - 1) & (STAGES - 1), tid);
        asm volatile("cp.async.commit_group;");

        int st = kt & (STAGES - 1);
        uint32_t a_stage = sb + SMEM_A + st * A_BYTES;
        uint32_t b_stage = sb + SMEM_B + st * B_BYTES;

#pragma unroll
        for (int ks = 0; ks < 4; ks++) {
            uint32_t aF[2][4], bF[4][4];
#pragma unroll
            for (int i = 0; i < 2; i++)
                ldsm4(aF[i], a_stage + swz128(aoff[i] + ks * 32));
#pragma unroll
            for (int j = 0; j < 4; j++)
                ldsm4(bF[j], b_stage + swz128(boff[j] + ks * 32));
#pragma unroll
            for (int i = 0; i < 2; i++) {
#pragma unroll
                for (int j = 0; j < 4; j++) {
                    mma16816(acc[i][2 * j],     aF[i], bF[j][0], bF[j][2]);
                    mma16816(acc[i][2 * j + 1], aF[i], bF[j][1], bF[j][3]);
                }
            }
        }
        __syncthreads();
    }

    // epilogue: fp16-round each element, store as float2
    int rq = lane >> 2;             // 0..7
    int cq = (lane & 3) * 2;        // 0,2,4,6
#pragma unroll
    for (int i = 0; i < 2; i++) {
        int mbase = m0 + warp_m * 32 + i * 16 + rq;
#pragma unroll
        for (int jj = 0; jj < 8; jj++) {
            int nidx = n0 + warp_n * 64 + jj * 8 + cq;
            float2 lo = make_float2(r16(acc[i][jj][0]), r16(acc[i][jj][1]));
            float2 hi = make_float2(r16(acc[i][jj][2]), r16(acc[i][jj][3]));
            *reinterpret_cast<float2*>(out + (size_t)mbase * NDIM + nidx) = lo;
            *reinterpret_cast<float2*>(out + (size_t)(mbase + 8) * NDIM + nidx) = hi;
        }
    }
}

// ---------------- launch ----------------
extern "C" void kernel_launch(void* const* d_in, const int* in_sizes, int n_in,
                              void* d_out, int out_size) {
    (void)in_sizes; (void)n_in; (void)out_size;
    const float* x   = (const float*)d_in[0];
    const int*   w   = (const int*)d_in[1];
    const float* sc  = (const float*)d_in[2];
    const float* off = (const float*)d_in[3];
    float* out = (float*)d_out;

    cudaFuncSetAttribute(gemm_kernel, cudaFuncAttributeMaxDynamicSharedMemorySize, SMEM_TOTAL);

    xconv_kernel<<<(MDIM * KDIM) / (256 * 4), 256>>>(x);
    dequant_kernel<<<NDIM, 256>>>(w, sc, off);
    gemm_kernel<<<(MDIM / BM) * (NDIM / BN), THREADS, SMEM_TOTAL>>>(out);
}

// round 5
// speedup vs baseline: 1.0078x; 1.0078x over previous
#include <cuda_runtime.h>
#include <cuda_fp16.h>
#include <cstdint>

// ---------------- problem constants ----------------
#define MDIM 8192      // B*S = 4*2048
#define NDIM 16384     // D_OUT
#define KDIM 4096      // D_IN

#define BM 128
#define BN 256
#define BK 64
#define STAGES 3
#define NKCHUNK (KDIM / BK)   // 64
#define THREADS 256

// SMEM layout (dynamic): per stage A(16KB) + B(32KB); 128B rows, SW128 swizzle
#define A_BYTES (BM * 128)                 // 16384
#define B_BYTES (BN * 128)                 // 32768
#define STAGE_BYTES (A_BYTES + B_BYTES)    // 49152
#define SMEM_TOTAL (STAGES * STAGE_BYTES)  // 147456

// static device scratch (allocation-free rule): dequantized W (fp16) + x (fp16)
__device__ __half g_wdeq[(size_t)NDIM * KDIM];   // 128 MiB
__device__ __half g_xh[(size_t)MDIM * KDIM];     // 64 MiB

// ---------------- PTX helpers (compute_103-safe only) ----------------
__device__ __forceinline__ uint32_t smem_u32(const void* p) {
    uint32_t a;
    asm("{ .reg .u64 t; cvta.to.shared.u64 t, %1; cvt.u32.u64 %0, t; }" : "=r"(a) : "l"(p));
    return a;
}

__device__ __forceinline__ uint32_t swz128(uint32_t b) {
    return b ^ ((b >> 3) & 0x70);
}

__device__ __forceinline__ void cp_async16(uint32_t dst, const void* src) {
    asm volatile("cp.async.cg.shared.global [%0], [%1], 16;" :: "r"(dst), "l"(src));
}

__device__ __forceinline__ void ldsm4(uint32_t* r, uint32_t addr) {
    asm volatile("ldmatrix.sync.aligned.m8n8.x4.shared.b16 {%0,%1,%2,%3}, [%4];"
                 : "=r"(r[0]), "=r"(r[1]), "=r"(r[2]), "=r"(r[3]) : "r"(addr));
}

__device__ __forceinline__ void mma16816(float* c, const uint32_t* a, uint32_t b0, uint32_t b1) {
    asm volatile(
        "mma.sync.aligned.m16n8k16.row.col.f32.f16.f16.f32 "
        "{%0,%1,%2,%3}, {%4,%5,%6,%7}, {%8,%9}, {%0,%1,%2,%3};"
        : "+f"(c[0]), "+f"(c[1]), "+f"(c[2]), "+f"(c[3])
        : "r"(a[0]), "r"(a[1]), "r"(a[2]), "r"(a[3]), "r"(b0), "r"(b1));
}

// round fp32 accumulator through fp16 (match reference .astype(float16))
__device__ __forceinline__ float r16(float f) {
    return __half2float(__float2half_rn(f));
}

// ---------------- dequant kernel (int32 carrier -> fp16, exact fp16 math) ----
__global__ __launch_bounds__(256) void dequant_kernel(const int* __restrict__ w,
                                                      const float* __restrict__ sc,
                                                      const float* __restrict__ off) {
    int row = blockIdx.x;
    int t = threadIdx.x;
    __half2 s2 = __half2half2(__float2half(sc[row]));
    __half2 o2 = __half2half2(__float2half(off[row]));
    const int4* src = reinterpret_cast<const int4*>(w + (size_t)row * KDIM);
    __half2* dstrow = reinterpret_cast<__half2*>(g_wdeq + (size_t)row * KDIM);
#pragma unroll
    for (int u = 0; u < 4; u++) {
        int4 v = src[u * 256 + t];
        __half2 p0 = __halves2half2(__int2half_rn(v.x), __int2half_rn(v.y));
        __half2 p1 = __halves2half2(__int2half_rn(v.z), __int2half_rn(v.w));
        __half2 r0 = __hmul2(__hadd2(p0, o2), s2);
        __half2 r1 = __hmul2(__hadd2(p1, o2), s2);
        uint2 pk = make_uint2(*reinterpret_cast<uint32_t*>(&r0),
                              *reinterpret_cast<uint32_t*>(&r1));
        *reinterpret_cast<uint2*>(dstrow + (u * 256 + t) * 2) = pk;
    }
}

// ---------------- x convert kernel (fp32 -> fp16, exact) ----------------
__global__ __launch_bounds__(256) void xconv_kernel(const float* __restrict__ x) {
    size_t i = (size_t)blockIdx.x * 256 + threadIdx.x;   // one float4 each
    float4 v = reinterpret_cast<const float4*>(x)[i];
    __half2 h0 = __floats2half2_rn(v.x, v.y);
    __half2 h1 = __floats2half2_rn(v.z, v.w);
    uint2 pk = make_uint2(*reinterpret_cast<uint32_t*>(&h0),
                          *reinterpret_cast<uint32_t*>(&h1));
    reinterpret_cast<uint2*>(g_xh)[i] = pk;
}

// ---------------- stage loader ----------------
// A: 128 rows x 64 halfs (128B, SW128). B: 256 rows x 64 halfs.
__device__ __forceinline__ void load_stage(uint32_t sb, const __half* __restrict__ xh,
                                           const __half* __restrict__ wd,
                                           int m0, int n0, int chunk, int st, int tid) {
    int kc = chunk * BK;
    uint32_t a_base = sb + st * STAGE_BYTES;
#pragma unroll
    for (int i = 0; i < 4; i++) {
        int idx = i * THREADS + tid;      // 1024 x 16B
        int r = idx >> 3, seg = idx & 7;
        uint32_t dst = a_base + swz128(r * 128 + seg * 16);
        cp_async16(dst, xh + (size_t)(m0 + r) * KDIM + kc + seg * 8);
    }
    uint32_t b_base = a_base + A_BYTES;
#pragma unroll
    for (int i = 0; i < 8; i++) {
        int idx = i * THREADS + tid;      // 2048 x 16B
        int r = idx >> 3, seg = idx & 7;
        uint32_t dst = b_base + swz128(r * 128 + seg * 16);
        cp_async16(dst, wd + (size_t)(n0 + r) * KDIM + kc + seg * 8);
    }
}

// ---------------- HMMA GEMM kernel: 128x256 CTA tile, 64x64 warp tile ------
__global__ __launch_bounds__(THREADS, 1) void gemm_kernel(float* __restrict__ out) {
    extern __shared__ char smem[];
    uint32_t sb = smem_u32(smem);
    int tid = threadIdx.x;
    int wid = tid >> 5, lane = tid & 31;
    int warp_m = wid & 1;       // 0..1  (64 rows each)
    int warp_n = wid >> 1;      // 0..3  (64 cols each)

    // tile mapping with GROUP_M=8 swizzle for L2 locality
    int pid = blockIdx.x;
    const int TM = MDIM / BM, TN = NDIM / BN;   // 64 x 64
    const int GROUP = 8;
    int per = GROUP * TN;
    int g = pid / per;
    int first = g * GROUP;
    int gsz = (GROUP < TM - first) ? GROUP : (TM - first);
    int mt = first + (pid % gsz);
    int nt = (pid % per) / gsz;
    int m0 = mt * BM, n0 = nt * BN;

    const __half* wd = g_wdeq;
    const __half* xh = g_xh;

    float acc[4][8][4];
#pragma unroll
    for (int i = 0; i < 4; i++)
#pragma unroll
        for (int j = 0; j < 8; j++)
#pragma unroll
            for (int q = 0; q < 4; q++) acc[i][j][q] = 0.0f;

    // ldmatrix x4 lane->address mapping (16-row tiles, 16 k-halfs):
    int lrow = lane & 15;
    int khalf = lane >> 4;
    uint32_t aoff[4], boff[4];
#pragma unroll
    for (int i = 0; i < 4; i++)
        aoff[i] = (uint32_t)((warp_m * 64 + i * 16 + lrow) * 128 + khalf * 16);
#pragma unroll
    for (int j = 0; j < 4; j++)
        boff[j] = (uint32_t)((warp_n * 64 + j * 16 + lrow) * 128 + khalf * 16);

    // prologue: chunks 0..STAGES-2
#pragma unroll
    for (int s = 0; s < STAGES - 1; s++) {
        load_stage(sb, xh, wd, m0, n0, s, s, tid);
        asm volatile("cp.async.commit_group;");
    }

    for (int kt = 0; kt < NKCHUNK; kt++) {
        asm volatile("cp.async.wait_group 1;");   // chunk kt resident
        __syncthreads();                          // single barrier per chunk

        // prefetch chunk kt+STAGES-1 into stage freed at iter kt-1 (safe: after barrier)
        if (kt + STAGES - 1 < NKCHUNK) {
            int fs = (kt + STAGES - 1) % STAGES;
            load_stage(sb, xh, wd, m0, n0, kt + STAGES - 1, fs, tid);
        }
        asm volatile("cp.async.commit_group;");

        int st = kt % STAGES;
        uint32_t a_stage = sb + st * STAGE_BYTES;
        uint32_t b_stage = a_stage + A_BYTES;

#pragma unroll
        for (int ks = 0; ks < 4; ks++) {
            uint32_t aF[4][4], bF[4][4];
#pragma unroll
            for (int i = 0; i < 4; i++)
                ldsm4(aF[i], a_stage + swz128(aoff[i] + ks * 32));
#pragma unroll
            for (int j = 0; j < 4; j++)
                ldsm4(bF[j], b_stage + swz128(boff[j] + ks * 32));
#pragma unroll
            for (int i = 0; i < 4; i++) {
#pragma unroll
                for (int j = 0; j < 4; j++) {
                    mma16816(acc[i][2 * j],     aF[i], bF[j][0], bF[j][2]);
                    mma16816(acc[i][2 * j + 1], aF[i], bF[j][1], bF[j][3]);
                }
            }
        }
    }

    // epilogue: fp16-round each element, store as float2
    int rq = lane >> 2;             // 0..7
    int cq = (lane & 3) * 2;        // 0,2,4,6
#pragma unroll
    for (int i = 0; i < 4; i++) {
        int mbase = m0 + warp_m * 64 + i * 16 + rq;
#pragma unroll
        for (int jj = 0; jj < 8; jj++) {
            int nidx = n0 + warp_n * 64 + jj * 8 + cq;
            float2 lo = make_float2(r16(acc[i][jj][0]), r16(acc[i][jj][1]));
            float2 hi = make_float2(r16(acc[i][jj][2]), r16(acc[i][jj][3]));
            *reinterpret_cast<float2*>(out + (size_t)mbase * NDIM + nidx) = lo;
            *reinterpret_cast<float2*>(out + (size_t)(mbase + 8) * NDIM + nidx) = hi;
        }
    }
}

// ---------------- launch ----------------
extern "C" void kernel_launch(void* const* d_in, const int* in_sizes, int n_in,
                              void* d_out, int out_size) {
    (void)in_sizes; (void)n_in; (void)out_size;
    const float* x   = (const float*)d_in[0];
    const int*   w   = (const int*)d_in[1];
    const float* sc  = (const float*)d_in[2];
    const float* off = (const float*)d_in[3];
    float* out = (float*)d_out;

    cudaFuncSetAttribute(gemm_kernel, cudaFuncAttributeMaxDynamicSharedMemorySize, SMEM_TOTAL);

    xconv_kernel<<<(MDIM * KDIM) / (256 * 4), 256>>>(x);
    dequant_kernel<<<NDIM, 256>>>(w, sc, off);
    gemm_kernel<<<(MDIM / BM) * (NDIM / BN), THREADS, SMEM_TOTAL>>>(out);
}

// round 6
// speedup vs baseline: 1.1319x; 1.1232x over previous
#include <cuda_runtime.h>
#include <cuda_fp16.h>
#include <cstdint>

// ---------------- problem constants ----------------
#define MDIM 8192      // B*S = 4*2048
#define NDIM 16384     // D_OUT
#define KDIM 4096      // D_IN

#define BM 128
#define BN 128
#define BK 64
#define STAGES 2
#define NKCHUNK (KDIM / BK)   // 64
#define THREADS 256

// SMEM: per stage A(16KB)+B(16KB); 128B rows, SW128 swizzle
#define A_BYTES (BM * 128)                 // 16384
#define B_BYTES (BN * 128)                 // 16384
#define STAGE_BYTES (A_BYTES + B_BYTES)    // 32768
#define SMEM_TOTAL (STAGES * STAGE_BYTES)  // 65536  -> 2 CTAs/SM

// static device scratch: dequantized W (fp16) + x (fp16)
__device__ __half g_wdeq[(size_t)NDIM * KDIM];   // 128 MiB
__device__ __half g_xh[(size_t)MDIM * KDIM];     // 64 MiB

// ---------------- PTX helpers (compute_103-safe only) ----------------
__device__ __forceinline__ uint32_t smem_u32(const void* p) {
    uint32_t a;
    asm("{ .reg .u64 t; cvta.to.shared.u64 t, %1; cvt.u32.u64 %0, t; }" : "=r"(a) : "l"(p));
    return a;
}

__device__ __forceinline__ uint32_t swz128(uint32_t b) {
    return b ^ ((b >> 3) & 0x70);
}

__device__ __forceinline__ void cp_async16(uint32_t dst, const void* src) {
    asm volatile("cp.async.cg.shared.global [%0], [%1], 16;" :: "r"(dst), "l"(src));
}

__device__ __forceinline__ void ldsm4(uint32_t* r, uint32_t addr) {
    asm volatile("ldmatrix.sync.aligned.m8n8.x4.shared.b16 {%0,%1,%2,%3}, [%4];"
                 : "=r"(r[0]), "=r"(r[1]), "=r"(r[2]), "=r"(r[3]) : "r"(addr));
}

__device__ __forceinline__ void mma16816(float* c, const uint32_t* a, uint32_t b0, uint32_t b1) {
    asm volatile(
        "mma.sync.aligned.m16n8k16.row.col.f32.f16.f16.f32 "
        "{%0,%1,%2,%3}, {%4,%5,%6,%7}, {%8,%9}, {%0,%1,%2,%3};"
        : "+f"(c[0]), "+f"(c[1]), "+f"(c[2]), "+f"(c[3])
        : "r"(a[0]), "r"(a[1]), "r"(a[2]), "r"(a[3]), "r"(b0), "r"(b1));
}

// round fp32 accumulator through fp16 (match reference .astype(float16))
__device__ __forceinline__ float r16(float f) {
    return __half2float(__float2half_rn(f));
}

// ---------------- fused prep kernel ----------------
// blocks [0, NDIM): dequant one W row (int32 carrier -> fp16, exact fp16 math)
// blocks [NDIM, NDIM+MDIM): convert one x row fp32 -> fp16
__global__ __launch_bounds__(256) void prep_kernel(const float* __restrict__ x,
                                                   const int* __restrict__ w,
                                                   const float* __restrict__ sc,
                                                   const float* __restrict__ off) {
    int b = blockIdx.x;
    int t = threadIdx.x;
    if (b < NDIM) {
        int row = b;
        __half2 s2 = __half2half2(__float2half(sc[row]));
        __half2 o2 = __half2half2(__float2half(off[row]));
        const int4* src = reinterpret_cast<const int4*>(w + (size_t)row * KDIM);
        __half2* dstrow = reinterpret_cast<__half2*>(g_wdeq + (size_t)row * KDIM);
#pragma unroll
        for (int u = 0; u < 4; u++) {
            int4 v = src[u * 256 + t];
            __half2 p0 = __halves2half2(__int2half_rn(v.x), __int2half_rn(v.y));
            __half2 p1 = __halves2half2(__int2half_rn(v.z), __int2half_rn(v.w));
            __half2 r0 = __hmul2(__hadd2(p0, o2), s2);
            __half2 r1 = __hmul2(__hadd2(p1, o2), s2);
            uint2 pk = make_uint2(*reinterpret_cast<uint32_t*>(&r0),
                                  *reinterpret_cast<uint32_t*>(&r1));
            *reinterpret_cast<uint2*>(dstrow + (u * 256 + t) * 2) = pk;
        }
    } else {
        int row = b - NDIM;
        const float4* src = reinterpret_cast<const float4*>(x + (size_t)row * KDIM);
        uint2* dstrow = reinterpret_cast<uint2*>(g_xh + (size_t)row * KDIM);
#pragma unroll
        for (int u = 0; u < 4; u++) {
            float4 v = src[u * 256 + t];
            __half2 h0 = __floats2half2_rn(v.x, v.y);
            __half2 h1 = __floats2half2_rn(v.z, v.w);
            dstrow[u * 256 + t] = make_uint2(*reinterpret_cast<uint32_t*>(&h0),
                                             *reinterpret_cast<uint32_t*>(&h1));
        }
    }
}

// ---------------- stage loader ----------------
// A: 128 rows x 64 halfs (128B rows, SW128). B: 128 rows x 64 halfs.
__device__ __forceinline__ void load_stage(uint32_t sb, const __half* __restrict__ xh,
                                           const __half* __restrict__ wd,
                                           int m0, int n0, int chunk, int st, int tid) {
    int kc = chunk * BK;
    uint32_t a_base = sb + st * STAGE_BYTES;
#pragma unroll
    for (int i = 0; i < 4; i++) {
        int idx = i * THREADS + tid;      // 1024 x 16B
        int r = idx >> 3, seg = idx & 7;
        uint32_t dst = a_base + swz128(r * 128 + seg * 16);
        cp_async16(dst, xh + (size_t)(m0 + r) * KDIM + kc + seg * 8);
    }
    uint32_t b_base = a_base + A_BYTES;
#pragma unroll
    for (int i = 0; i < 4; i++) {
        int idx = i * THREADS + tid;      // 1024 x 16B
        int r = idx >> 3, seg = idx & 7;
        uint32_t dst = b_base + swz128(r * 128 + seg * 16);
        cp_async16(dst, wd + (size_t)(n0 + r) * KDIM + kc + seg * 8);
    }
}

// ---------------- HMMA GEMM: 128x128 CTA, 64x32 warp tile, 2 CTAs/SM ------
__global__ __launch_bounds__(THREADS, 2) void gemm_kernel(float* __restrict__ out) {
    extern __shared__ char smem[];
    uint32_t sb = smem_u32(smem);
    int tid = threadIdx.x;
    int wid = tid >> 5, lane = tid & 31;
    int warp_m = wid & 1;       // 0..1  (64 rows)
    int warp_n = wid >> 1;      // 0..3  (32 cols)

    // tile mapping with GROUP_M=8 swizzle for L2 locality
    int pid = blockIdx.x;
    const int TM = MDIM / BM, TN = NDIM / BN;   // 64 x 128
    const int GROUP = 8;
    int per = GROUP * TN;
    int g = pid / per;
    int first = g * GROUP;
    int gsz = (GROUP < TM - first) ? GROUP : (TM - first);
    int mt = first + (pid % gsz);
    int nt = (pid % per) / gsz;
    int m0 = mt * BM, n0 = nt * BN;

    const __half* wd = g_wdeq;
    const __half* xh = g_xh;

    float acc[4][4][4];
#pragma unroll
    for (int i = 0; i < 4; i++)
#pragma unroll
        for (int j = 0; j < 4; j++)
#pragma unroll
            for (int q = 0; q < 4; q++) acc[i][j][q] = 0.0f;

    // ldmatrix x4 lane->address mapping (16-row tiles, 16 k-halfs)
    int lrow = lane & 15;
    int khalf = lane >> 4;
    uint32_t aoff[4], boff[2];
#pragma unroll
    for (int i = 0; i < 4; i++)
        aoff[i] = (uint32_t)((warp_m * 64 + i * 16 + lrow) * 128 + khalf * 16);
#pragma unroll
    for (int j = 0; j < 2; j++)
        boff[j] = (uint32_t)((warp_n * 32 + j * 16 + lrow) * 128 + khalf * 16);

    // prologue: stage 0
    load_stage(sb, xh, wd, m0, n0, 0, 0, tid);
    asm volatile("cp.async.commit_group;");

    for (int kt = 0; kt < NKCHUNK; kt++) {
        asm volatile("cp.async.wait_group 0;");   // stage kt resident
        __syncthreads();                          // + all warps done with kt-1

        if (kt + 1 < NKCHUNK)
            load_stage(sb, xh, wd, m0, n0, kt + 1, (kt + 1) & 1, tid);
        asm volatile("cp.async.commit_group;");

        uint32_t a_stage = sb + (kt & 1) * STAGE_BYTES;
        uint32_t b_stage = a_stage + A_BYTES;

#pragma unroll
        for (int ks = 0; ks < 4; ks++) {
            uint32_t aF[4][4], bF[2][4];
#pragma unroll
            for (int i = 0; i < 4; i++)
                ldsm4(aF[i], a_stage + swz128(aoff[i] + ks * 32));
#pragma unroll
            for (int j = 0; j < 2; j++)
                ldsm4(bF[j], b_stage + swz128(boff[j] + ks * 32));
#pragma unroll
            for (int i = 0; i < 4; i++) {
#pragma unroll
                for (int j = 0; j < 2; j++) {
                    mma16816(acc[i][2 * j],     aF[i], bF[j][0], bF[j][2]);
                    mma16816(acc[i][2 * j + 1], aF[i], bF[j][1], bF[j][3]);
                }
            }
        }
    }

    // epilogue: fp16-round each element, store as float2
    int rq = lane >> 2;             // 0..7
    int cq = (lane & 3) * 2;        // 0,2,4,6
#pragma unroll
    for (int i = 0; i < 4; i++) {
        int mbase = m0 + warp_m * 64 + i * 16 + rq;
#pragma unroll
        for (int jj = 0; jj < 4; jj++) {
            int nidx = n0 + warp_n * 32 + jj * 8 + cq;
            float2 lo = make_float2(r16(acc[i][jj][0]), r16(acc[i][jj][1]));
            float2 hi = make_float2(r16(acc[i][jj][2]), r16(acc[i][jj][3]));
            *reinterpret_cast<float2*>(out + (size_t)mbase * NDIM + nidx) = lo;
            *reinterpret_cast<float2*>(out + (size_t)(mbase + 8) * NDIM + nidx) = hi;
        }
    }
}

// ---------------- launch ----------------
extern "C" void kernel_launch(void* const* d_in, const int* in_sizes, int n_in,
                              void* d_out, int out_size) {
    (void)in_sizes; (void)n_in; (void)out_size;
    const float* x   = (const float*)d_in[0];
    const int*   w   = (const int*)d_in[1];
    const float* sc  = (const float*)d_in[2];
    const float* off = (const float*)d_in[3];
    float* out = (float*)d_out;

    cudaFuncSetAttribute(gemm_kernel, cudaFuncAttributeMaxDynamicSharedMemorySize, SMEM_TOTAL);

    prep_kernel<<<NDIM + MDIM, 256>>>(x, w, sc, off);
    gemm_kernel<<<(MDIM / BM) * (NDIM / BN), THREADS, SMEM_TOTAL>>>(out);
}